// round 1
// baseline (speedup 1.0000x reference)
#include <cuda_runtime.h>
#include <cuda_bf16.h>

// LightGCN: 3-layer normalized graph propagation.
// N = 150000 nodes, DIM = 64, E = 1.25M edges.

#define NUM_USERS 100000
#define NUM_ITEMS 50000
#define NN        150000
#define DIM       64
#define EDGES     1250000

#define NQ  (NN * DIM / 4)        // float4 count of an embedding buffer: 2.4M
#define UQ  (NUM_USERS * DIM / 4) // float4 count of user slice: 1.6M

// Scratch (device globals: allocation-free per harness rules). ~120MB total.
__device__ float g_bufA[NN * DIM];
__device__ float g_bufB[NN * DIM];
__device__ float g_acc[NN * DIM];
__device__ float g_deg[NN];
__device__ float g_norm[EDGES];
__device__ int   g_is32;   // 1 if edge_index is int32, 0 if int64

// ---------------------------------------------------------------------------
// Detect edge_index dtype. If the buffer is int32, reading it as int64 packs
// two values (lo + hi<<32); hi is a random index in [0,150000) so the value is
// >= 2^32 with overwhelming probability. 256 samples -> certain.
// ---------------------------------------------------------------------------
__global__ void detect_kernel(const void* edge) {
    __shared__ int flag;
    if (threadIdx.x == 0) flag = 0;
    __syncthreads();
    const long long* p = (const long long*)edge;
    long long v = p[threadIdx.x * 4];   // spread samples, max offset 1020 int64 = 8160B (safe either way)
    if (v < 0 || v >= (long long)NN) atomicOr(&flag, 1);
    __syncthreads();
    if (threadIdx.x == 0) g_is32 = flag;
}

__device__ __forceinline__ void load_edge(const void* edge, int e, long long& s, long long& d) {
    if (g_is32) {
        const int* ei = (const int*)edge;
        s = ei[e];
        d = ei[EDGES + e];
    } else {
        const long long* ei = (const long long*)edge;
        s = ei[e];
        d = ei[EDGES + e];
    }
}

// ---------------------------------------------------------------------------
// init: bufA = emb (user||item), acc = emb, bufB = 0, deg = 0
// ---------------------------------------------------------------------------
__global__ void init_kernel(const float* __restrict__ uw, const float* __restrict__ iw) {
    int i = blockIdx.x * blockDim.x + threadIdx.x;
    if (i < NQ) {
        float4 v;
        if (i < UQ) v = ((const float4*)uw)[i];
        else        v = ((const float4*)iw)[i - UQ];
        ((float4*)g_bufA)[i] = v;
        ((float4*)g_acc)[i]  = v;
        ((float4*)g_bufB)[i] = make_float4(0.f, 0.f, 0.f, 0.f);
    }
    if (i < NN) g_deg[i] = 0.f;
}

// ---------------------------------------------------------------------------
// deg[dst] += 1
// ---------------------------------------------------------------------------
__global__ void deg_kernel(const void* edge) {
    int e = blockIdx.x * blockDim.x + threadIdx.x;
    if (e >= EDGES) return;
    long long d;
    if (g_is32) d = ((const int*)edge)[EDGES + e];
    else        d = ((const long long*)edge)[EDGES + e];
    atomicAdd(&g_deg[d], 1.0f);
}

// ---------------------------------------------------------------------------
// norm[e] = rsqrt(deg[s]*deg[d]) with 0 guard
// ---------------------------------------------------------------------------
__global__ void norm_kernel(const void* edge) {
    int e = blockIdx.x * blockDim.x + threadIdx.x;
    if (e >= EDGES) return;
    long long s, d;
    load_edge(edge, e, s, d);
    float p = g_deg[s] * g_deg[d];
    g_norm[e] = (p > 0.f) ? rsqrtf(p) : 0.f;
}

// ---------------------------------------------------------------------------
// scatter: next[dst] += cur[src] * norm[e]
// 16 threads per edge, each handles 4 consecutive floats (one float4 gather
// + 4 atomicAdds). Row working sets (cur+next = 77MB) live in L2.
// ---------------------------------------------------------------------------
__global__ void scatter_kernel(const void* edge,
                               const float* __restrict__ cur,
                               float* __restrict__ nxt) {
    long long t = (long long)blockIdx.x * blockDim.x + threadIdx.x;
    int e = (int)(t >> 4);
    int c = (int)(t & 15);
    if (e >= EDGES) return;
    float w = g_norm[e];
    if (w == 0.f) return;
    long long s, d;
    load_edge(edge, e, s, d);
    float4 v = ((const float4*)cur)[s * 16 + c];
    float* o = nxt + d * 64 + c * 4;
    atomicAdd(o + 0, v.x * w);
    atomicAdd(o + 1, v.y * w);
    atomicAdd(o + 2, v.z * w);
    atomicAdd(o + 3, v.w * w);
}

// ---------------------------------------------------------------------------
// acc += layer_result; zero the buffer that receives the NEXT layer's scatter
// ---------------------------------------------------------------------------
__global__ void addzero_kernel(const float* __restrict__ b, float* __restrict__ zbuf) {
    int i = blockIdx.x * blockDim.x + threadIdx.x;
    if (i >= NQ) return;
    float4 v = ((const float4*)b)[i];
    float4 a = ((float4*)g_acc)[i];
    a.x += v.x; a.y += v.y; a.z += v.z; a.w += v.w;
    ((float4*)g_acc)[i]  = a;
    ((float4*)zbuf)[i]   = make_float4(0.f, 0.f, 0.f, 0.f);
}

// ---------------------------------------------------------------------------
// final: all = (acc + last_layer) / 4.
// Output layout: [all (N*64)] [user (NU*64)] [item (NI*64)] — the user||item
// half is byte-identical to all, so write each value twice.
// ---------------------------------------------------------------------------
__global__ void final_kernel(const float* __restrict__ b, float* __restrict__ out) {
    int i = blockIdx.x * blockDim.x + threadIdx.x;
    if (i >= NQ) return;
    float4 a = ((const float4*)g_acc)[i];
    float4 v = ((const float4*)b)[i];
    float4 r;
    r.x = (a.x + v.x) * 0.25f;
    r.y = (a.y + v.y) * 0.25f;
    r.z = (a.z + v.z) * 0.25f;
    r.w = (a.w + v.w) * 0.25f;
    float4* o = (float4*)out;
    o[i]      = r;
    o[NQ + i] = r;
}

// ---------------------------------------------------------------------------
extern "C" void kernel_launch(void* const* d_in, const int* in_sizes, int n_in,
                              void* d_out, int out_size) {
    const void*  edge = d_in[0];                   // int64 or int32 [2, E]
    const float* uw   = (const float*)d_in[1];     // [NUM_USERS, 64]
    const float* iw   = (const float*)d_in[2];     // [NUM_ITEMS, 64]
    float*       out  = (float*)d_out;

    const int T = 256;
    const int grid_q  = (NQ + T - 1) / T;                 // elementwise passes
    const int grid_e  = (EDGES + T - 1) / T;              // per-edge passes
    const long long st = (long long)EDGES * 16;
    const int grid_s  = (int)((st + T - 1) / T);          // scatter passes

    float* A = nullptr;
    float* B = nullptr;
    cudaGetSymbolAddress((void**)&A, g_bufA);
    cudaGetSymbolAddress((void**)&B, g_bufB);

    detect_kernel<<<1, 256>>>(edge);
    init_kernel<<<grid_q, T>>>(uw, iw);
    deg_kernel<<<grid_e, T>>>(edge);
    norm_kernel<<<grid_e, T>>>(edge);

    // layer 1: A -> B (B already zeroed by init); acc += B; zero A
    scatter_kernel<<<grid_s, T>>>(edge, A, B);
    addzero_kernel<<<grid_q, T>>>(B, A);

    // layer 2: B -> A; acc += A; zero B
    scatter_kernel<<<grid_s, T>>>(edge, B, A);
    addzero_kernel<<<grid_q, T>>>(A, B);

    // layer 3: A -> B; final fuses acc += B and /4 and the duplicated output
    scatter_kernel<<<grid_s, T>>>(edge, A, B);
    final_kernel<<<grid_q, T>>>(B, out);
}

// round 2
// speedup vs baseline: 3.0920x; 3.0920x over previous
#include <cuda_runtime.h>
#include <cuda_bf16.h>

// LightGCN 3-layer propagation, CSR (dst-sorted) atomic-free version.
// N = 150000, DIM = 64, E = 1.25M.

#define NUM_USERS 100000
#define NUM_ITEMS 50000
#define NN        150000
#define DIM       64
#define EDGES     1250000

#define NQ  (NN * 16)          // float4 count of one embedding buffer (2.4M)
#define UQ  (NUM_USERS * 16)   // float4 count of user slice

#define SCAN_B 256
#define NBLK   ((NN + SCAN_B - 1) / SCAN_B)   // 587

// Device-global scratch (allocation-free per harness rules). ~127MB.
__device__ float g_bufA[NN * DIM];
__device__ float g_bufB[NN * DIM];
__device__ float g_acc [NN * DIM];
__device__ int   g_cnt [NN];        // in-degree (int)
__device__ int   g_off [NN + 1];    // CSR row offsets
__device__ int   g_cursor[NN];      // fill cursors
__device__ int   g_srcs[EDGES];     // src node per edge, sorted by dst
__device__ float g_ws  [EDGES];     // edge weight, sorted by dst
__device__ int   g_bsum[NBLK];      // scan block sums
__device__ int   g_is32;            // edge_index dtype flag

// ---------------------------------------------------------------------------
// Detect edge_index dtype: int32 data read as int64 packs two random indices,
// giving values >= 2^32 with overwhelming probability.
// ---------------------------------------------------------------------------
__global__ void detect_kernel(const void* edge) {
    __shared__ int flag;
    if (threadIdx.x == 0) flag = 0;
    __syncthreads();
    const long long* p = (const long long*)edge;
    long long v = p[threadIdx.x * 4];
    if (v < 0 || v >= (long long)NN) atomicOr(&flag, 1);
    __syncthreads();
    if (threadIdx.x == 0) g_is32 = flag;
}

__device__ __forceinline__ void load_edge(const void* edge, int e, int& s, int& d) {
    if (g_is32) {
        const int* ei = (const int*)edge;
        s = ei[e];
        d = ei[EDGES + e];
    } else {
        const long long* ei = (const long long*)edge;
        s = (int)ei[e];
        d = (int)ei[EDGES + e];
    }
}

// ---------------------------------------------------------------------------
// init: bufA = emb (user||item), acc = emb, cnt = 0
// ---------------------------------------------------------------------------
__global__ void init_kernel(const float* __restrict__ uw, const float* __restrict__ iw) {
    int i = blockIdx.x * blockDim.x + threadIdx.x;
    if (i < NQ) {
        float4 v;
        if (i < UQ) v = ((const float4*)uw)[i];
        else        v = ((const float4*)iw)[i - UQ];
        ((float4*)g_bufA)[i] = v;
        ((float4*)g_acc)[i]  = v;
    }
    if (i < NN) g_cnt[i] = 0;
}

// ---------------------------------------------------------------------------
// in-degree histogram
// ---------------------------------------------------------------------------
__global__ void hist_kernel(const void* edge) {
    int e = blockIdx.x * blockDim.x + threadIdx.x;
    if (e >= EDGES) return;
    int d;
    if (g_is32) d = ((const int*)edge)[EDGES + e];
    else        d = (int)((const long long*)edge)[EDGES + e];
    atomicAdd(&g_cnt[d], 1);
}

// ---------------------------------------------------------------------------
// 3-kernel exclusive scan over g_cnt -> g_off
// ---------------------------------------------------------------------------
__global__ void scan1_kernel() {
    __shared__ int sh[SCAN_B];
    int i = blockIdx.x * SCAN_B + threadIdx.x;
    int v = (i < NN) ? g_cnt[i] : 0;
    sh[threadIdx.x] = v;
    __syncthreads();
    for (int o = 1; o < SCAN_B; o <<= 1) {
        int t = (threadIdx.x >= o) ? sh[threadIdx.x - o] : 0;
        __syncthreads();
        if (threadIdx.x >= o) sh[threadIdx.x] += t;
        __syncthreads();
    }
    if (i < NN) g_off[i] = sh[threadIdx.x] - v;   // exclusive within block
    if (threadIdx.x == SCAN_B - 1) g_bsum[blockIdx.x] = sh[threadIdx.x];
}

__global__ void scan2_kernel() {
    __shared__ int sh[1024];
    int i = threadIdx.x;
    int v = (i < NBLK) ? g_bsum[i] : 0;
    sh[i] = v;
    __syncthreads();
    for (int o = 1; o < 1024; o <<= 1) {
        int t = (i >= o) ? sh[i - o] : 0;
        __syncthreads();
        if (i >= o) sh[i] += t;
        __syncthreads();
    }
    if (i < NBLK) g_bsum[i] = sh[i] - v;          // exclusive block prefix
    if (i == 0) g_off[NN] = EDGES;
}

__global__ void scan3_kernel() {
    int i = blockIdx.x * SCAN_B + threadIdx.x;
    if (i >= NN) return;
    int o = g_off[i] + g_bsum[blockIdx.x];
    g_off[i]    = o;
    g_cursor[i] = o;
}

// ---------------------------------------------------------------------------
// CSR fill: sorted-by-dst (src, w) lists; w = rsqrt(deg_s*deg_d), 0-guarded.
// ---------------------------------------------------------------------------
__global__ void fill_kernel(const void* edge) {
    int e = blockIdx.x * blockDim.x + threadIdx.x;
    if (e >= EDGES) return;
    int s, d;
    load_edge(edge, e, s, d);
    float p = (float)g_cnt[s] * (float)g_cnt[d];
    float w = (p > 0.f) ? rsqrtf(p) : 0.f;
    int pos = atomicAdd(&g_cursor[d], 1);
    g_srcs[pos] = s;
    g_ws[pos]   = w;
}

// ---------------------------------------------------------------------------
// Propagate: nxt[n] = sum_{e in in(n)} w_e * cur[src_e], atomic-free.
// 16 lanes per node; lane c owns float4 #c of the 64-float row.
// MODE 0: write nxt and acc += row.  MODE 1: out = (acc+row)/4, duplicated.
// ---------------------------------------------------------------------------
template<int MODE>
__global__ void prop_kernel(const float* __restrict__ cur,
                            float* __restrict__ nxt,
                            float* __restrict__ out) {
    int n = blockIdx.x * (blockDim.x >> 4) + (threadIdx.x >> 4);
    int c = threadIdx.x & 15;
    if (n >= NN) return;
    int j   = g_off[n];
    int end = g_off[n + 1];
    float4 r = make_float4(0.f, 0.f, 0.f, 0.f);

    // unroll-by-2 for MLP
    for (; j + 1 < end; j += 2) {
        int   s0 = g_srcs[j];
        int   s1 = g_srcs[j + 1];
        float w0 = g_ws[j];
        float w1 = g_ws[j + 1];
        float4 v0 = ((const float4*)cur)[s0 * 16 + c];
        float4 v1 = ((const float4*)cur)[s1 * 16 + c];
        r.x += v0.x * w0 + v1.x * w1;
        r.y += v0.y * w0 + v1.y * w1;
        r.z += v0.z * w0 + v1.z * w1;
        r.w += v0.w * w0 + v1.w * w1;
    }
    if (j < end) {
        int   s = g_srcs[j];
        float w = g_ws[j];
        float4 v = ((const float4*)cur)[s * 16 + c];
        r.x += v.x * w; r.y += v.y * w; r.z += v.z * w; r.w += v.w * w;
    }

    int idx = n * 16 + c;
    if (MODE == 0) {
        ((float4*)nxt)[idx] = r;
        float4 a = ((float4*)g_acc)[idx];
        a.x += r.x; a.y += r.y; a.z += r.z; a.w += r.w;
        ((float4*)g_acc)[idx] = a;
    } else {
        float4 a = ((float4*)g_acc)[idx];
        float4 o;
        o.x = (a.x + r.x) * 0.25f;
        o.y = (a.y + r.y) * 0.25f;
        o.z = (a.z + r.z) * 0.25f;
        o.w = (a.w + r.w) * 0.25f;
        float4* op = (float4*)out;
        op[idx]      = o;
        op[NQ + idx] = o;
    }
}

// ---------------------------------------------------------------------------
extern "C" void kernel_launch(void* const* d_in, const int* in_sizes, int n_in,
                              void* d_out, int out_size) {
    const void*  edge = d_in[0];
    const float* uw   = (const float*)d_in[1];
    const float* iw   = (const float*)d_in[2];
    float*       out  = (float*)d_out;

    float* A = nullptr;
    float* B = nullptr;
    cudaGetSymbolAddress((void**)&A, g_bufA);
    cudaGetSymbolAddress((void**)&B, g_bufB);

    const int T = 256;
    const int grid_q = (NQ + T - 1) / T;
    const int grid_e = (EDGES + T - 1) / T;
    const int grid_p = (NN * 16 + T - 1) / T;   // 16 lanes/node

    detect_kernel<<<1, 256>>>(edge);
    init_kernel<<<grid_q, T>>>(uw, iw);
    hist_kernel<<<grid_e, T>>>(edge);
    scan1_kernel<<<NBLK, SCAN_B>>>();
    scan2_kernel<<<1, 1024>>>();
    scan3_kernel<<<NBLK, SCAN_B>>>();
    fill_kernel<<<grid_e, T>>>(edge);

    prop_kernel<0><<<grid_p, T>>>(A, B, nullptr);   // layer 1: A -> B, acc += B
    prop_kernel<0><<<grid_p, T>>>(B, A, nullptr);   // layer 2: B -> A, acc += A
    prop_kernel<1><<<grid_p, T>>>(A, nullptr, out); // layer 3 + finalize + dup
}

// round 3
// speedup vs baseline: 3.3800x; 1.0932x over previous
#include <cuda_runtime.h>
#include <cuda_bf16.h>

// LightGCN 3-layer propagation. CSR (dst-sorted), atomic-free reduction,
// no acc buffer (layer-1 gathers straight from inputs; layer-3 finalizes
// in registers).

#define NUM_USERS 100000
#define NUM_ITEMS 50000
#define NN        150000
#define DIM       64
#define EDGES     1250000

#define NQ  (NN * 16)          // float4 count of one embedding buffer
#define UQ  (NUM_USERS * 16)

#define SCAN_B 256
#define NBLK   ((NN + SCAN_B - 1) / SCAN_B)   // 587

// Device-global scratch. bufA/bufB = 77MB, edge pairs = 10MB.
__device__ float g_bufA[NN * DIM];
__device__ float g_bufB[NN * DIM];
__device__ int   g_cnt [NN];        // in-degree
__device__ int   g_off [NN + 1];    // CSR row offsets
__device__ int   g_cursor[NN];      // fill cursors
__device__ int2  g_edge[EDGES];     // {src, __float_as_int(w)} sorted by dst
__device__ int   g_bsum[NBLK];      // scan block sums
__device__ int   g_is32;            // edge_index dtype flag

// ---------------------------------------------------------------------------
// detect dtype (block 0) + zero g_cnt (all blocks).
// int32 data read as int64 packs two random indices -> >= 2^32 w.h.p.
// ---------------------------------------------------------------------------
__global__ void detect_zero_kernel(const void* edge) {
    int i = blockIdx.x * blockDim.x + threadIdx.x;
    if (i < NN) g_cnt[i] = 0;
    if (blockIdx.x == 0) {
        __shared__ int flag;
        if (threadIdx.x == 0) flag = 0;
        __syncthreads();
        long long v = ((const long long*)edge)[threadIdx.x * 4];
        if (v < 0 || v >= (long long)NN) atomicOr(&flag, 1);
        __syncthreads();
        if (threadIdx.x == 0) g_is32 = flag;
    }
}

__device__ __forceinline__ void load_edge(const void* edge, int e, int& s, int& d) {
    if (g_is32) {
        const int* ei = (const int*)edge;
        s = ei[e];
        d = ei[EDGES + e];
    } else {
        const long long* ei = (const long long*)edge;
        s = (int)ei[e];
        d = (int)ei[EDGES + e];
    }
}

// ---------------------------------------------------------------------------
// in-degree histogram
// ---------------------------------------------------------------------------
__global__ void hist_kernel(const void* edge) {
    int e = blockIdx.x * blockDim.x + threadIdx.x;
    if (e >= EDGES) return;
    int d;
    if (g_is32) d = ((const int*)edge)[EDGES + e];
    else        d = (int)((const long long*)edge)[EDGES + e];
    atomicAdd(&g_cnt[d], 1);
}

// ---------------------------------------------------------------------------
// shuffle-based exclusive scan, 3 kernels
// ---------------------------------------------------------------------------
__device__ __forceinline__ int warp_incl_scan(int v) {
    #pragma unroll
    for (int o = 1; o < 32; o <<= 1) {
        int t = __shfl_up_sync(0xffffffffu, v, o);
        if ((threadIdx.x & 31) >= o) v += t;
    }
    return v;
}

__global__ void scan1_kernel() {
    __shared__ int wsum[8];
    int i = blockIdx.x * SCAN_B + threadIdx.x;
    int v = (i < NN) ? g_cnt[i] : 0;
    int incl = warp_incl_scan(v);
    int wid = threadIdx.x >> 5, lid = threadIdx.x & 31;
    if (lid == 31) wsum[wid] = incl;
    __syncthreads();
    if (wid == 0) {
        int s = (lid < 8) ? wsum[lid] : 0;
        #pragma unroll
        for (int o = 1; o < 8; o <<= 1) {
            int t = __shfl_up_sync(0xffffffffu, s, o);
            if (lid >= o) s += t;
        }
        if (lid < 8) wsum[lid] = s;
    }
    __syncthreads();
    int base = (wid > 0) ? wsum[wid - 1] : 0;
    if (i < NN) g_off[i] = base + incl - v;   // block-local exclusive
    if (threadIdx.x == SCAN_B - 1) g_bsum[blockIdx.x] = base + incl;
}

__global__ void scan2_kernel() {   // 1024 threads, NBLK=587 elements
    __shared__ int wsum[32];
    int i = threadIdx.x;
    int v = (i < NBLK) ? g_bsum[i] : 0;
    int incl = warp_incl_scan(v);
    int wid = i >> 5, lid = i & 31;
    if (lid == 31) wsum[wid] = incl;
    __syncthreads();
    if (wid == 0) {
        int s = wsum[lid];
        #pragma unroll
        for (int o = 1; o < 32; o <<= 1) {
            int t = __shfl_up_sync(0xffffffffu, s, o);
            if (lid >= o) s += t;
        }
        wsum[lid] = s;
    }
    __syncthreads();
    int base = (wid > 0) ? wsum[wid - 1] : 0;
    if (i < NBLK) g_bsum[i] = base + incl - v;   // exclusive block prefix
    if (i == 0) g_off[NN] = EDGES;
}

__global__ void scan3_kernel() {
    int i = blockIdx.x * SCAN_B + threadIdx.x;
    if (i >= NN) return;
    int o = g_off[i] + g_bsum[blockIdx.x];
    g_off[i]    = o;
    g_cursor[i] = o;
}

// ---------------------------------------------------------------------------
// CSR fill: {src, w} pairs sorted by dst; w = rsqrt(deg_s*deg_d), 0-guarded.
// ---------------------------------------------------------------------------
__global__ void fill_kernel(const void* edge) {
    int e = blockIdx.x * blockDim.x + threadIdx.x;
    if (e >= EDGES) return;
    int s, d;
    load_edge(edge, e, s, d);
    float p = (float)g_cnt[s] * (float)g_cnt[d];
    float w = (p > 0.f) ? rsqrtf(p) : 0.f;
    int pos = atomicAdd(&g_cursor[d], 1);
    g_edge[pos] = make_int2(s, __float_as_int(w));
}

// ---------------------------------------------------------------------------
// Propagate. 16 lanes per node; lane c owns float4 #c of the 64-float row.
// MODE 0: layer 1 — gather from uw/iw, write nxt (=c1).
// MODE 1: middle  — gather from cur, write nxt.
// MODE 2: final   — gather from cur(=c2); out = (emb + c1 + c2 + r)/4, dup'd.
// ---------------------------------------------------------------------------
template<int MODE>
__global__ void __launch_bounds__(256)
prop_kernel(const float* __restrict__ cur,
            const float* __restrict__ uw,
            const float* __restrict__ iw,
            const float* __restrict__ c1,
            float* __restrict__ nxt,
            float* __restrict__ out) {
    int n = blockIdx.x * (blockDim.x >> 4) + (threadIdx.x >> 4);
    int c = threadIdx.x & 15;
    if (n >= NN) return;
    int j   = g_off[n];
    int end = g_off[n + 1];
    float4 r = make_float4(0.f, 0.f, 0.f, 0.f);

    const int2* ge = g_edge;
    for (; j + 1 < end; j += 2) {
        int2 e0 = ge[j];
        int2 e1 = ge[j + 1];
        float w0 = __int_as_float(e0.y);
        float w1 = __int_as_float(e1.y);
        float4 v0, v1;
        if (MODE == 0) {
            v0 = (e0.x < NUM_USERS) ? ((const float4*)uw)[e0.x * 16 + c]
                                    : ((const float4*)iw)[(e0.x - NUM_USERS) * 16 + c];
            v1 = (e1.x < NUM_USERS) ? ((const float4*)uw)[e1.x * 16 + c]
                                    : ((const float4*)iw)[(e1.x - NUM_USERS) * 16 + c];
        } else {
            v0 = ((const float4*)cur)[e0.x * 16 + c];
            v1 = ((const float4*)cur)[e1.x * 16 + c];
        }
        r.x += v0.x * w0 + v1.x * w1;
        r.y += v0.y * w0 + v1.y * w1;
        r.z += v0.z * w0 + v1.z * w1;
        r.w += v0.w * w0 + v1.w * w1;
    }
    if (j < end) {
        int2 e0 = ge[j];
        float w0 = __int_as_float(e0.y);
        float4 v0;
        if (MODE == 0) {
            v0 = (e0.x < NUM_USERS) ? ((const float4*)uw)[e0.x * 16 + c]
                                    : ((const float4*)iw)[(e0.x - NUM_USERS) * 16 + c];
        } else {
            v0 = ((const float4*)cur)[e0.x * 16 + c];
        }
        r.x += v0.x * w0; r.y += v0.y * w0; r.z += v0.z * w0; r.w += v0.w * w0;
    }

    int idx = n * 16 + c;
    if (MODE == 2) {
        float4 e = (n < NUM_USERS) ? ((const float4*)uw)[idx]
                                   : ((const float4*)iw)[idx - UQ];
        float4 a = ((const float4*)c1)[idx];   // c1 = layer-1 result
        float4 b = ((const float4*)cur)[idx];  // c2 = layer-2 result
        float4 o;
        o.x = (e.x + a.x + b.x + r.x) * 0.25f;
        o.y = (e.y + a.y + b.y + r.y) * 0.25f;
        o.z = (e.z + a.z + b.z + r.z) * 0.25f;
        o.w = (e.w + a.w + b.w + r.w) * 0.25f;
        float4* op = (float4*)out;
        op[idx]      = o;
        op[NQ + idx] = o;
    } else {
        ((float4*)nxt)[idx] = r;
    }
}

// ---------------------------------------------------------------------------
extern "C" void kernel_launch(void* const* d_in, const int* in_sizes, int n_in,
                              void* d_out, int out_size) {
    const void*  edge = d_in[0];
    const float* uw   = (const float*)d_in[1];
    const float* iw   = (const float*)d_in[2];
    float*       out  = (float*)d_out;

    float* A = nullptr;
    float* B = nullptr;
    cudaGetSymbolAddress((void**)&A, g_bufA);
    cudaGetSymbolAddress((void**)&B, g_bufB);

    const int T = 256;
    const int grid_e = (EDGES + T - 1) / T;
    const int grid_p = (NN * 16 + T - 1) / T;

    detect_zero_kernel<<<NBLK, SCAN_B>>>(edge);
    hist_kernel<<<grid_e, T>>>(edge);
    scan1_kernel<<<NBLK, SCAN_B>>>();
    scan2_kernel<<<1, 1024>>>();
    scan3_kernel<<<NBLK, SCAN_B>>>();
    fill_kernel<<<grid_e, T>>>(edge);

    // layer 1: emb -> B (c1)
    prop_kernel<0><<<grid_p, T>>>(nullptr, uw, iw, nullptr, B, nullptr);
    // layer 2: B -> A (c2)
    prop_kernel<1><<<grid_p, T>>>(B, nullptr, nullptr, nullptr, A, nullptr);
    // layer 3: gather A, finalize with emb + B + A, duplicated output
    prop_kernel<2><<<grid_p, T>>>(A, uw, iw, B, nullptr, out);
}

// round 4
// speedup vs baseline: 3.8921x; 1.1515x over previous
#include <cuda_runtime.h>
#include <cuda_bf16.h>

// LightGCN 3-layer propagation. CSR (dst-sorted), atomic-free reduction.
// Preprocessing: detect -> hist+rank -> scan1 -> scan2 -> fill (rank-addressed,
// no cursor atomics, no scan3: consumers add block-sum on the fly).

#define NUM_USERS 100000
#define NUM_ITEMS 50000
#define NN        150000
#define DIM       64
#define EDGES     1250000

#define NQ  (NN * 16)          // float4 count of one embedding buffer
#define UQ  (NUM_USERS * 16)

#define SCAN_B 256
#define NBLK   ((NN + SCAN_B - 1) / SCAN_B)   // 586
#define OFFSZ  (NBLK * SCAN_B)                // padded offset array size

// Device-global scratch. bufA/bufB = 77MB, edges = 10MB, rank = 5MB.
__device__ float g_bufA[NN * DIM];
__device__ float g_bufB[NN * DIM];
__device__ int   g_cnt [NN];        // in-degree
__device__ int   g_rank[EDGES];     // per-edge arrival rank within its dst
__device__ int   g_off [OFFSZ + 1]; // block-LOCAL exclusive prefix of cnt
__device__ int   g_bsum[NBLK];      // exclusive block sums
__device__ int2  g_edge[EDGES];     // {src, __float_as_int(w)} sorted by dst
__device__ int   g_is32;            // edge_index dtype flag

// ---------------------------------------------------------------------------
// detect dtype (block 0) + zero g_cnt (all blocks).
// ---------------------------------------------------------------------------
__global__ void detect_zero_kernel(const void* edge) {
    int i = blockIdx.x * blockDim.x + threadIdx.x;
    if (i < NN) g_cnt[i] = 0;
    if (blockIdx.x == 0) {
        __shared__ int flag;
        if (threadIdx.x == 0) flag = 0;
        __syncthreads();
        long long v = ((const long long*)edge)[threadIdx.x * 4];
        if (v < 0 || v >= (long long)NN) atomicOr(&flag, 1);
        __syncthreads();
        if (threadIdx.x == 0) g_is32 = flag;
    }
}

__device__ __forceinline__ void load_edge(const void* edge, int e, int& s, int& d) {
    if (g_is32) {
        const int* ei = (const int*)edge;
        s = ei[e];
        d = ei[EDGES + e];
    } else {
        const long long* ei = (const long long*)edge;
        s = (int)ei[e];
        d = (int)ei[EDGES + e];
    }
}

// ---------------------------------------------------------------------------
// histogram + per-edge rank (atomicAdd return value)
// ---------------------------------------------------------------------------
__global__ void histrank_kernel(const void* edge) {
    int e = blockIdx.x * blockDim.x + threadIdx.x;
    if (e >= EDGES) return;
    int d;
    if (g_is32) d = ((const int*)edge)[EDGES + e];
    else        d = (int)((const long long*)edge)[EDGES + e];
    g_rank[e] = atomicAdd(&g_cnt[d], 1);
}

// ---------------------------------------------------------------------------
// shuffle-based scan: block-local exclusive (scan1) + block sums (scan2)
// ---------------------------------------------------------------------------
__device__ __forceinline__ int warp_incl_scan(int v, int lid) {
    #pragma unroll
    for (int o = 1; o < 32; o <<= 1) {
        int t = __shfl_up_sync(0xffffffffu, v, o);
        if (lid >= o) v += t;
    }
    return v;
}

__global__ void scan1_kernel() {
    __shared__ int wsum[8];
    int i = blockIdx.x * SCAN_B + threadIdx.x;
    int v = (i < NN) ? g_cnt[i] : 0;
    int wid = threadIdx.x >> 5, lid = threadIdx.x & 31;
    int incl = warp_incl_scan(v, lid);
    if (lid == 31) wsum[wid] = incl;
    __syncthreads();
    if (wid == 0) {
        int s = (lid < 8) ? wsum[lid] : 0;
        #pragma unroll
        for (int o = 1; o < 8; o <<= 1) {
            int t = __shfl_up_sync(0xffffffffu, s, o);
            if (lid >= o) s += t;
        }
        if (lid < 8) wsum[lid] = s;
    }
    __syncthreads();
    int base = (wid > 0) ? wsum[wid - 1] : 0;
    g_off[i] = base + incl - v;                       // block-local exclusive
    if (threadIdx.x == SCAN_B - 1) g_bsum[blockIdx.x] = base + incl;
    if (i == 0) g_off[OFFSZ] = 0;                     // padding guard
}

__global__ void scan2_kernel() {   // 1 block, NBLK=586 elements, 640 threads
    __shared__ int wsum[20];
    int i = threadIdx.x;
    int lid = i & 31, wid = i >> 5;
    int v = (i < NBLK) ? g_bsum[i] : 0;
    int incl = warp_incl_scan(v, lid);
    if (lid == 31) wsum[wid] = incl;
    __syncthreads();
    if (wid == 0) {
        int s = (lid < 20) ? wsum[lid] : 0;
        #pragma unroll
        for (int o = 1; o < 32; o <<= 1) {
            int t = __shfl_up_sync(0xffffffffu, s, o);
            if (lid >= o) s += t;
        }
        if (lid < 20) wsum[lid] = s;
    }
    __syncthreads();
    int base = (wid > 0) ? wsum[wid - 1] : 0;
    if (i < NBLK) g_bsum[i] = base + incl - v;        // exclusive block prefix
}

// ---------------------------------------------------------------------------
// CSR fill: pos = local_off[d] + bsum[d>>8] + rank[e]. No atomics.
// w = rsqrt(deg_s*deg_d), 0-guarded.
// ---------------------------------------------------------------------------
__global__ void fill_kernel(const void* edge) {
    int e = blockIdx.x * blockDim.x + threadIdx.x;
    if (e >= EDGES) return;
    int s, d;
    load_edge(edge, e, s, d);
    float p = (float)g_cnt[s] * (float)g_cnt[d];
    float w = (p > 0.f) ? rsqrtf(p) : 0.f;
    int pos = g_off[d] + g_bsum[d >> 8] + g_rank[e];
    g_edge[pos] = make_int2(s, __float_as_int(w));
}

// ---------------------------------------------------------------------------
// Propagate. 16 lanes per node; lane c owns float4 #c of the 64-float row.
// Unroll-4 gather batches for MLP. Offsets reconstructed as local+bsum.
// MODE 0: layer 1 (gather from uw/iw) -> nxt.
// MODE 1: middle (gather from cur) -> nxt.
// MODE 2: final: out = (emb + c1 + cur + r)/4, duplicated.
// ---------------------------------------------------------------------------
template<int MODE>
__device__ __forceinline__ float4 gather(const float* __restrict__ cur,
                                         const float* __restrict__ uw,
                                         const float* __restrict__ iw,
                                         int s, int c) {
    if (MODE == 0) {
        const float4* base = (s < NUM_USERS)
            ? (const float4*)uw + (long long)s * 16
            : (const float4*)iw + (long long)(s - NUM_USERS) * 16;
        return base[c];
    }
    return ((const float4*)cur)[(long long)s * 16 + c];
}

template<int MODE>
__global__ void __launch_bounds__(256)
prop_kernel(const float* __restrict__ cur,
            const float* __restrict__ uw,
            const float* __restrict__ iw,
            const float* __restrict__ c1,
            float* __restrict__ nxt,
            float* __restrict__ out) {
    int n = blockIdx.x * (blockDim.x >> 4) + (threadIdx.x >> 4);
    int c = threadIdx.x & 15;
    if (n >= NN) return;
    int j   = g_off[n]     + g_bsum[n >> 8];
    int end = g_off[n + 1] + g_bsum[(n + 1) >> 8];
    float4 r = make_float4(0.f, 0.f, 0.f, 0.f);

    const int2* ge = g_edge;
    for (; j + 4 <= end; j += 4) {
        int2 e0 = ge[j];
        int2 e1 = ge[j + 1];
        int2 e2 = ge[j + 2];
        int2 e3 = ge[j + 3];
        float4 v0 = gather<MODE>(cur, uw, iw, e0.x, c);
        float4 v1 = gather<MODE>(cur, uw, iw, e1.x, c);
        float4 v2 = gather<MODE>(cur, uw, iw, e2.x, c);
        float4 v3 = gather<MODE>(cur, uw, iw, e3.x, c);
        float w0 = __int_as_float(e0.y), w1 = __int_as_float(e1.y);
        float w2 = __int_as_float(e2.y), w3 = __int_as_float(e3.y);
        r.x += v0.x * w0 + v1.x * w1 + v2.x * w2 + v3.x * w3;
        r.y += v0.y * w0 + v1.y * w1 + v2.y * w2 + v3.y * w3;
        r.z += v0.z * w0 + v1.z * w1 + v2.z * w2 + v3.z * w3;
        r.w += v0.w * w0 + v1.w * w1 + v2.w * w2 + v3.w * w3;
    }
    #pragma unroll 1
    for (; j < end; ++j) {
        int2 e0 = ge[j];
        float w0 = __int_as_float(e0.y);
        float4 v0 = gather<MODE>(cur, uw, iw, e0.x, c);
        r.x += v0.x * w0; r.y += v0.y * w0; r.z += v0.z * w0; r.w += v0.w * w0;
    }

    int idx = n * 16 + c;
    if (MODE == 2) {
        float4 e = (n < NUM_USERS) ? ((const float4*)uw)[idx]
                                   : ((const float4*)iw)[idx - UQ];
        float4 a = ((const float4*)c1)[idx];   // layer-1 result
        float4 b = ((const float4*)cur)[idx];  // layer-2 result
        float4 o;
        o.x = (e.x + a.x + b.x + r.x) * 0.25f;
        o.y = (e.y + a.y + b.y + r.y) * 0.25f;
        o.z = (e.z + a.z + b.z + r.z) * 0.25f;
        o.w = (e.w + a.w + b.w + r.w) * 0.25f;
        float4* op = (float4*)out;
        op[idx]      = o;
        op[NQ + idx] = o;
    } else {
        ((float4*)nxt)[idx] = r;
    }
}

// ---------------------------------------------------------------------------
extern "C" void kernel_launch(void* const* d_in, const int* in_sizes, int n_in,
                              void* d_out, int out_size) {
    const void*  edge = d_in[0];
    const float* uw   = (const float*)d_in[1];
    const float* iw   = (const float*)d_in[2];
    float*       out  = (float*)d_out;

    float* A = nullptr;
    float* B = nullptr;
    cudaGetSymbolAddress((void**)&A, g_bufA);
    cudaGetSymbolAddress((void**)&B, g_bufB);

    const int T = 256;
    const int grid_e = (EDGES + T - 1) / T;
    const int grid_p = (NN * 16 + T - 1) / T;

    detect_zero_kernel<<<NBLK, SCAN_B>>>(edge);
    histrank_kernel<<<grid_e, T>>>(edge);
    scan1_kernel<<<NBLK, SCAN_B>>>();
    scan2_kernel<<<1, 640>>>();
    fill_kernel<<<grid_e, T>>>(edge);

    // layer 1: emb -> B (c1)
    prop_kernel<0><<<grid_p, T>>>(nullptr, uw, iw, nullptr, B, nullptr);
    // layer 2: B -> A (c2)
    prop_kernel<1><<<grid_p, T>>>(B, nullptr, nullptr, nullptr, A, nullptr);
    // layer 3: gather A, finalize with emb + B + A, duplicated output
    prop_kernel<2><<<grid_p, T>>>(A, uw, iw, B, nullptr, out);
}